// round 16
// baseline (speedup 1.0000x reference)
#include <cuda_runtime.h>
#include <math.h>
#include <stdint.h>

#define NPTS  4096
#define BATCH 8
#define KNN   20
#define NG    (BATCH*NPTS)
#define NROWS (NG*KNN)
#define ENCNEG 0u   /* bottom element for encf order (memset-compatible) */

// ---------------- scratch (device globals; no allocations) ----------------
__device__ float    g_y1[(size_t)NROWS*64];
__device__ float    g_y2[(size_t)NROWS*64];
__device__ float    g_y3[(size_t)NROWS*128];
__device__ float    g_y5[(size_t)NG*512];
__device__ float    g_cat[(size_t)NG*512];
__device__ uint32_t g_mx[(size_t)NG*512];   // mx1|mx2|mx3|mx4 @ 0|64NG|128NG|256NG
__device__ int      g_idx[NROWS];
__device__ uint32_t g_wtf[307200];          // tf32 W2|W3|W4|W5 @ 0|4096|12288|45056
__device__ float    g_sum[8*1024];          // 8 replicas (anti atomic-contention)
__device__ float    g_sq[8*1024];
__device__ float    g_sc[1024];
__device__ float    g_sh[1024];

__device__ __forceinline__ uint32_t f2tf(float f) {
    uint32_t r; asm("cvt.rna.tf32.f32 %0, %1;" : "=r"(r) : "f"(f)); return r;
}
__device__ __forceinline__ void mma_tf32(float* c, const uint32_t* a, const uint32_t* b) {
    asm volatile(
        "mma.sync.aligned.m16n8k8.row.col.f32.tf32.tf32.f32 "
        "{%0,%1,%2,%3}, {%4,%5,%6,%7}, {%8,%9}, {%0,%1,%2,%3};"
        : "+f"(c[0]), "+f"(c[1]), "+f"(c[2]), "+f"(c[3])
        : "r"(a[0]), "r"(a[1]), "r"(a[2]), "r"(a[3]), "r"(b[0]), "r"(b[1]));
}
__device__ __forceinline__ uint32_t encf(float f) {
    uint32_t u = __float_as_uint(f);
    return (u & 0x80000000u) ? ~u : (u | 0x80000000u);
}
__device__ __forceinline__ float decf(uint32_t e) {
    uint32_t u = (e & 0x80000000u) ? (e & 0x7FFFFFFFu) : ~e;
    return __uint_as_float(u);
}
__device__ __forceinline__ void cp_async16(uint32_t saddr, const void* gptr) {
    asm volatile("cp.async.ca.shared.global [%0], [%1], 16;" :: "r"(saddr), "l"(gptr));
}
#define CP_COMMIT() asm volatile("cp.async.commit_group;" ::: "memory")
#define CP_WAIT0()  asm volatile("cp.async.wait_group 0;"  ::: "memory")

// -------- kNN (+ fused W f32->tf32 pre-convert using idle threads) ---------
__global__ void knn_kernel(const float* __restrict__ x, int* __restrict__ oidx,
                           const float* __restrict__ W2, const float* __restrict__ W3,
                           const float* __restrict__ W4, const float* __restrict__ W5,
                           uint32_t* __restrict__ wtf)
{
    extern __shared__ float4 pts[];
    {
        int lid = (blockIdx.y * gridDim.x + blockIdx.x) * 256 + threadIdx.x;
#pragma unroll
        for (int q = 0; q < 8; q++) {
            int i = lid + q*32768;
            if (i < 4096)  wtf[i]         = f2tf(W2[i]);
            if (i < 8192)  wtf[4096 + i]  = f2tf(W3[i]);
            if (i < 32768) wtf[12288 + i] = f2tf(W4[i]);
            wtf[45056 + i] = f2tf(W5[i]);
        }
    }
    const int b = blockIdx.y;
    const float* xb = x + (size_t)b * 3 * NPTS;
    for (int i = threadIdx.x; i < NPTS; i += 256) {
        float px = xb[i], py = xb[NPTS + i], pz = xb[2*NPTS + i];
        pts[i] = make_float4(px, py, pz, px*px + py*py + pz*pz);
    }
    __syncthreads();
    const int qi = blockIdx.x * 256 + threadIdx.x;
    const float4 q = pts[qi];
    const float q2x = 2.f*q.x, q2y = 2.f*q.y, q2z = 2.f*q.z, nqw = -q.w;

    float best[KNN]; int bidx[KNN];
#pragma unroll
    for (int m = 0; m < KNN; m++) {
        float4 p = pts[m];
        best[m] = fmaf(q2x, p.x, fmaf(q2y, p.y, fmaf(q2z, p.z, nqw - p.w)));
        bidx[m] = m;
    }
    float vmin = best[0]; int mpos = 0;
#pragma unroll
    for (int m = 1; m < KNN; m++) if (best[m] < vmin) { vmin = best[m]; mpos = m; }

    for (int j = KNN; j < NPTS; j++) {
        float4 p = pts[j];
        float v = fmaf(q2x, p.x, fmaf(q2y, p.y, fmaf(q2z, p.z, nqw - p.w)));
        if (v > vmin) {
#pragma unroll
            for (int m = 0; m < KNN; m++) if (m == mpos) { best[m] = v; bidx[m] = j; }
            vmin = best[0]; mpos = 0;
#pragma unroll
            for (int m = 1; m < KNN; m++) if (best[m] < vmin) { vmin = best[m]; mpos = m; }
        }
    }
    int* o = oidx + (size_t)(b * NPTS + qi) * KNN;
#pragma unroll
    for (int m = 0; m < KNN; m++) o[m] = bidx[m];
}

// ---------------- layer 1: gather + (6->64) + stats + raw max --------------
__global__ __launch_bounds__(128)
void layer1_kernel(const float* __restrict__ x, const int* __restrict__ idx,
                   const float* __restrict__ W1, float* __restrict__ y1,
                   float* __restrict__ sum_out, float* __restrict__ sq_out,
                   uint32_t* __restrict__ mx1)
{
    const int t    = threadIdx.x & 63;
    const int slot = threadIdx.x >> 6;
    float w[6];
#pragma unroll
    for (int c = 0; c < 6; c++) w[c] = W1[c*64 + t];
    float s = 0.f, qq = 0.f;
    const int g0 = blockIdx.x * 16;
    for (int it = 0; it < 8; it++) {
        const int g = g0 + it*2 + slot;
        const int b = g >> 12;
        const int n = g & (NPTS - 1);
        const float* xb = x + (size_t)b*3*NPTS;
        float base = fmaf(xb[n], w[3], fmaf(xb[NPTS+n], w[4], xb[2*NPTS+n]*w[5]));
        const int* ip = idx + (size_t)g*KNN;
        float* yp = y1 + (size_t)g*KNN*64 + t;
        float mxv = -3.4e38f;
#pragma unroll 4
        for (int k = 0; k < KNN; k++) {
            int j = ip[k];
            float v = fmaf(xb[j], w[0], fmaf(xb[NPTS+j], w[1], fmaf(xb[2*NPTS+j], w[2], base)));
            yp[(size_t)k*64] = v;
            s += v; qq = fmaf(v, v, qq);
            mxv = fmaxf(mxv, v);
        }
        mx1[(size_t)g*64 + t] = encf(mxv);
    }
    const int rep = (blockIdx.x & 7) * 1024;
    atomicAdd(&sum_out[rep + t], s);
    atomicAdd(&sq_out[rep + t],  qq);
}

// ---------------- bn finalize (sums 8 replicas) -----------------------------
__global__ void finalize_kernel(const float* __restrict__ sum, const float* __restrict__ sq,
                                const float* __restrict__ gam, const float* __restrict__ bet,
                                float* __restrict__ sc, float* __restrict__ sh, float inv_cnt)
{
    int c = threadIdx.x;
    float s = 0.f, q = 0.f;
#pragma unroll
    for (int r = 0; r < 8; r++) { s += sum[r*1024 + c]; q += sq[r*1024 + c]; }
    float m = s * inv_cnt;
    float v = q * inv_cnt - m*m;
    float scale = gam[c] * rsqrtf(v + 1e-5f);
    sc[c] = scale;
    sh[c] = bet[c] - m*scale;
}

// ------------- maxtrans: cat[g,off+c] = relu(dec(mx)*sc+sh) -----------------
template<int C>
__global__ void maxtrans_kernel(const uint32_t* __restrict__ mx, const float* __restrict__ sc,
                                const float* __restrict__ sh, float* __restrict__ cat, int off)
{
    int i = blockIdx.x*blockDim.x + threadIdx.x;
    int g = i / C, c = i & (C - 1);
    float v = decf(mx[i]);
    cat[(size_t)g*512 + off + c] = fmaxf(fmaf(v, sc[c], sh[c]), 0.f);
}

// ---------------------------------------------------------------------------
// Fused tf32 GEMM, 2-stage smem pipeline, de-contended bn-stats epilogue.
// Parameterized warp grid: WM x WN warps, warp tile (16*MI) x (8*NI).
// ---------------------------------------------------------------------------
template<int KD, int ND, int NT, int MI, int NI, bool BN_IN, bool MAXOUT, bool WRITE_Y>
__global__ __launch_bounds__((128/(MI*16))*(NT/(NI*8))*32)
void gemm_fused(const float* __restrict__ A, const uint32_t* __restrict__ Wtf,
                float* __restrict__ Y, const float* __restrict__ sc_in,
                const float* __restrict__ sh_in, float* __restrict__ gsum,
                float* __restrict__ gsq, uint32_t* __restrict__ gmx)
{
    constexpr int WM      = 128/(MI*16);
    constexpr int WN      = NT/(NI*8);
    constexpr int THREADS = WM*WN*32;
    constexpr int KC   = 32;
    constexpr int NCH  = KD/KC;
    constexpr int ASTR = 137;
    constexpr int BSTR = NT + 8;
    constexpr int WTN  = 8*NI;
    constexpr int AQ   = 128*(KC/4)/THREADS;
    constexpr int BQ   = KC*(NT/4)/THREADS;

    extern __shared__ uint32_t dsm[];
    uint32_t* As0 = dsm;
    uint32_t* Bs0 = dsm + 2*KC*ASTR;
    uint32_t* mxs = Bs0 + 2*KC*BSTR;
    __shared__ float ssc[KD];
    __shared__ float ssh[KD];
    const uint32_t bsAddr = (uint32_t)__cvta_generic_to_shared(Bs0);

    const int tid  = threadIdx.x;
    const int wid  = tid >> 5;
    const int lane = tid & 31;
    const int g    = lane >> 2;
    const int t    = lane & 3;
    const int warpM = wid % WM;
    const int warpN = wid / WM;
    const int rowBase = blockIdx.y * 128;
    const int colBase = blockIdx.x * NT;

    if (BN_IN)
        for (int i = tid; i < KD; i += THREADS) { ssc[i] = sc_in[i]; ssh[i] = sh_in[i]; }
    if (MAXOUT)
        for (int i = tid; i < 8*NT; i += THREADS) mxs[i] = ENCNEG;
    __syncthreads();

    float acc[MI][NI][4];
#pragma unroll
    for (int mi = 0; mi < MI; mi++)
#pragma unroll
        for (int ni = 0; ni < NI; ni++)
#pragma unroll
            for (int r = 0; r < 4; r++) acc[mi][ni][r] = 0.f;

    float4 aPre[AQ];

    // ---- prologue: chunk 0 into stage 0 ----
#pragma unroll
    for (int q = 0; q < BQ; q++) {
        int e = tid + q*THREADS;
        int k = e / (NT/4), c4 = (e % (NT/4)) * 4;
        cp_async16(bsAddr + (uint32_t)(k*BSTR + c4)*4,
                   Wtf + (size_t)k*ND + colBase + c4);
    }
    CP_COMMIT();
#pragma unroll
    for (int q = 0; q < AQ; q++) {
        int e = tid + q*THREADS;
        aPre[q] = *(const float4*)&A[(size_t)(rowBase + (e>>3))*KD + ((e&7)<<2)];
    }
    {
        uint32_t* Asw = As0;
#pragma unroll
        for (int q = 0; q < AQ; q++) {
            int e = tid + q*THREADS;
            int r = e >> 3, k4 = (e & 7) << 2;
            float4 v = aPre[q];
            if (BN_IN) {
                int c = k4;
                v.x = fmaxf(fmaf(v.x, ssc[c+0], ssh[c+0]), 0.f);
                v.y = fmaxf(fmaf(v.y, ssc[c+1], ssh[c+1]), 0.f);
                v.z = fmaxf(fmaf(v.z, ssc[c+2], ssh[c+2]), 0.f);
                v.w = fmaxf(fmaf(v.w, ssc[c+3], ssh[c+3]), 0.f);
            }
            Asw[(k4+0)*ASTR + r] = f2tf(v.x);
            Asw[(k4+1)*ASTR + r] = f2tf(v.y);
            Asw[(k4+2)*ASTR + r] = f2tf(v.z);
            Asw[(k4+3)*ASTR + r] = f2tf(v.w);
        }
    }
    CP_WAIT0();
    __syncthreads();

    for (int i = 0; i < NCH; i++) {
        const int s = i & 1;
        const int kb2 = (i+1)*KC;
        if (i + 1 < NCH) {
            const uint32_t bst = bsAddr + (uint32_t)((s^1)*KC*BSTR)*4;
#pragma unroll
            for (int q = 0; q < BQ; q++) {
                int e = tid + q*THREADS;
                int k = e / (NT/4), c4 = (e % (NT/4)) * 4;
                cp_async16(bst + (uint32_t)(k*BSTR + c4)*4,
                           Wtf + (size_t)(kb2 + k)*ND + colBase + c4);
            }
            CP_COMMIT();
#pragma unroll
            for (int q = 0; q < AQ; q++) {
                int e = tid + q*THREADS;
                aPre[q] = *(const float4*)&A[(size_t)(rowBase + (e>>3))*KD + kb2 + ((e&7)<<2)];
            }
        }
        const uint32_t* Asx = As0 + s*KC*ASTR;
        const uint32_t* Bsx = Bs0 + s*KC*BSTR;
#pragma unroll
        for (int k8 = 0; k8 < KC; k8 += 8) {
            uint32_t a[MI][4], b[NI][2];
#pragma unroll
            for (int mi = 0; mi < MI; mi++) {
                int m = warpM*(MI*16) + mi*16 + g;
                a[mi][0] = Asx[(k8 + t    )*ASTR + m    ];
                a[mi][1] = Asx[(k8 + t    )*ASTR + m + 8];
                a[mi][2] = Asx[(k8 + t + 4)*ASTR + m    ];
                a[mi][3] = Asx[(k8 + t + 4)*ASTR + m + 8];
            }
#pragma unroll
            for (int ni = 0; ni < NI; ni++) {
                int n = warpN*WTN + ni*8 + g;
                b[ni][0] = Bsx[(k8 + t    )*BSTR + n];
                b[ni][1] = Bsx[(k8 + t + 4)*BSTR + n];
            }
#pragma unroll
            for (int mi = 0; mi < MI; mi++)
#pragma unroll
                for (int ni = 0; ni < NI; ni++)
                    mma_tf32(acc[mi][ni], a[mi], b[ni]);
        }
        if (i + 1 < NCH) {
            uint32_t* Asw = As0 + (s^1)*KC*ASTR;
#pragma unroll
            for (int q = 0; q < AQ; q++) {
                int e = tid + q*THREADS;
                int r = e >> 3, k4 = (e & 7) << 2;
                float4 v = aPre[q];
                if (BN_IN) {
                    int c = kb2 + k4;
                    v.x = fmaxf(fmaf(v.x, ssc[c+0], ssh[c+0]), 0.f);
                    v.y = fmaxf(fmaf(v.y, ssc[c+1], ssh[c+1]), 0.f);
                    v.z = fmaxf(fmaf(v.z, ssc[c+2], ssh[c+2]), 0.f);
                    v.w = fmaxf(fmaf(v.w, ssc[c+3], ssh[c+3]), 0.f);
                }
                Asw[(k4+0)*ASTR + r] = f2tf(v.x);
                Asw[(k4+1)*ASTR + r] = f2tf(v.y);
                Asw[(k4+2)*ASTR + r] = f2tf(v.z);
                Asw[(k4+3)*ASTR + r] = f2tf(v.w);
            }
            CP_WAIT0();
        }
        __syncthreads();   // after this, As0 is dead -> reusable as scratch
    }

    const int col = colBase + warpN*WTN + 2*t;

    if (WRITE_Y) {
#pragma unroll
        for (int mi = 0; mi < MI; mi++) {
            size_t row0 = (size_t)rowBase + warpM*(MI*16) + mi*16 + g;
#pragma unroll
            for (int ni = 0; ni < NI; ni++) {
                *(float2*)&Y[row0*ND + col + ni*8] =
                    make_float2(acc[mi][ni][0], acc[mi][ni][1]);
                *(float2*)&Y[(row0+8)*ND + col + ni*8] =
                    make_float2(acc[mi][ni][2], acc[mi][ni][3]);
            }
        }
    }

    // ---- bn stats: shfl -> smem cross-warpM combine -> 8-replica RED ----
    float* red = (float*)As0;          // scratch: WM x NT cols x {sum,sq}
#pragma unroll
    for (int ni = 0; ni < NI; ni++) {
        float s0 = 0.f, q0 = 0.f, s1 = 0.f, q1 = 0.f;
#pragma unroll
        for (int mi = 0; mi < MI; mi++) {
            float v0 = acc[mi][ni][0], v2 = acc[mi][ni][2];
            float v1 = acc[mi][ni][1], v3 = acc[mi][ni][3];
            s0 += v0 + v2; q0 = fmaf(v0, v0, fmaf(v2, v2, q0));
            s1 += v1 + v3; q1 = fmaf(v1, v1, fmaf(v3, v3, q1));
        }
#pragma unroll
        for (int m = 4; m < 32; m <<= 1) {
            s0 += __shfl_xor_sync(0xffffffff, s0, m);
            q0 += __shfl_xor_sync(0xffffffff, q0, m);
            s1 += __shfl_xor_sync(0xffffffff, s1, m);
            q1 += __shfl_xor_sync(0xffffffff, q1, m);
        }
        if (g == 0) {
            int cl = warpN*WTN + 2*t + ni*8;
            red[(warpM*NT + cl    )*2 + 0] = s0;
            red[(warpM*NT + cl    )*2 + 1] = q0;
            red[(warpM*NT + cl + 1)*2 + 0] = s1;
            red[(warpM*NT + cl + 1)*2 + 1] = q1;
        }
    }
    __syncthreads();
    {
        const int rep = (blockIdx.y & 7) * 1024;
        for (int e = tid; e < NT; e += THREADS) {
            float s = 0.f, q = 0.f;
#pragma unroll
            for (int r = 0; r < WM; r++) {
                s += red[(r*NT+e)*2];
                q += red[(r*NT+e)*2+1];
            }
            atomicAdd(&gsum[rep + colBase + e], s);
            atomicAdd(&gsq [rep + colBase + e], q);
        }
    }

    // ---- raw max per (group, channel) ----
    if (MAXOUT) {
        const int colL = warpN*WTN + 2*t;
        const int gbase = rowBase / 20;
#pragma unroll
        for (int mi = 0; mi < MI; mi++) {
            int rl0 = warpM*(MI*16) + mi*16 + g;
            int gl0 = (rowBase + rl0) / 20 - gbase;
            int gl1 = (rowBase + rl0 + 8) / 20 - gbase;
#pragma unroll
            for (int ni = 0; ni < NI; ni++) {
                atomicMax(&mxs[gl0*NT + colL + ni*8    ], encf(acc[mi][ni][0]));
                atomicMax(&mxs[gl0*NT + colL + ni*8 + 1], encf(acc[mi][ni][1]));
                atomicMax(&mxs[gl1*NT + colL + ni*8    ], encf(acc[mi][ni][2]));
                atomicMax(&mxs[gl1*NT + colL + ni*8 + 1], encf(acc[mi][ni][3]));
            }
        }
        __syncthreads();
        int glast = (rowBase + 127) / 20;
        int ng = glast - gbase + 1;
        for (int e = tid; e < ng*NT; e += THREADS) {
            int gl = e / NT, cc = e - gl*NT;
            int gg = gbase + gl;
            uint32_t v = mxs[e];
            uint32_t* dst = &gmx[(size_t)gg*ND + colBase + cc];
            if (gg*20 >= rowBase && gg*20 + 20 <= rowBase + 128) *dst = v;
            else atomicMax(dst, v);
        }
    }
}

// ---------------- output: relu(bn(y5)) then (B,N,E) -> (B,E,N) --------------
__global__ void out_kernel(const float* __restrict__ y5, const float* __restrict__ sc,
                           const float* __restrict__ sh, float* __restrict__ out)
{
    __shared__ float tile[32][33];
    const int b = blockIdx.z;
    const int e0 = blockIdx.y * 32, n0 = blockIdx.x * 32;
    const int tx = threadIdx.x, ty = threadIdx.y;
    const int e = e0 + tx;
    const float scale = sc[e], shift = sh[e];
    for (int i = ty; i < 32; i += 8) {
        float v = y5[((size_t)b*NPTS + n0 + i)*512 + e];
        tile[i][tx] = fmaxf(fmaf(v, scale, shift), 0.f);
    }
    __syncthreads();
    for (int i = ty; i < 32; i += 8)
        out[((size_t)b*512 + e0 + i)*NPTS + n0 + tx] = tile[tx][i];
}

// ---------------------------------------------------------------------------
extern "C" void kernel_launch(void* const* d_in, const int* in_sizes, int n_in,
                              void* d_out, int out_size)
{
    const float* x  = (const float*)d_in[0];
    const float* W1 = (const float*)d_in[1];
    const float* W2 = (const float*)d_in[2];
    const float* W3 = (const float*)d_in[3];
    const float* W4 = (const float*)d_in[4];
    const float* W5 = (const float*)d_in[5];
    const float* g1 = (const float*)d_in[6];
    const float* b1 = (const float*)d_in[7];
    const float* g2 = (const float*)d_in[8];
    const float* b2 = (const float*)d_in[9];
    const float* g3 = (const float*)d_in[10];
    const float* b3 = (const float*)d_in[11];
    const float* g4 = (const float*)d_in[12];
    const float* b4 = (const float*)d_in[13];
    const float* g5 = (const float*)d_in[14];
    const float* b5 = (const float*)d_in[15];
    float* out = (float*)d_out;

    float *y1,*y2,*y3,*y5,*cat,*sum,*sq,*sc,*sh;
    uint32_t *mx,*wtf;
    int* idxp;
    cudaGetSymbolAddress((void**)&y1,  g_y1);
    cudaGetSymbolAddress((void**)&y2,  g_y2);
    cudaGetSymbolAddress((void**)&y3,  g_y3);
    cudaGetSymbolAddress((void**)&y5,  g_y5);
    cudaGetSymbolAddress((void**)&cat, g_cat);
    cudaGetSymbolAddress((void**)&mx,  g_mx);
    cudaGetSymbolAddress((void**)&idxp, g_idx);
    cudaGetSymbolAddress((void**)&wtf, g_wtf);
    cudaGetSymbolAddress((void**)&sum, g_sum);
    cudaGetSymbolAddress((void**)&sq,  g_sq);
    cudaGetSymbolAddress((void**)&sc,  g_sc);
    cudaGetSymbolAddress((void**)&sh,  g_sh);

    uint32_t* mx1 = mx;
    uint32_t* mx2 = mx + (size_t)NG*64;
    uint32_t* mx3 = mx + (size_t)NG*128;
    uint32_t* mx4 = mx + (size_t)NG*256;

    const float invR = 1.0f / (float)NROWS;
    const float invG = 1.0f / (float)NG;

    const int sm2 = (2*32*137 + 2*32*72  + 8*64 )*4;   // 55552
    const int sm3 = (2*32*137 + 2*32*136 + 8*128)*4;   // 73984
    const int sm4 = (2*32*137 + 2*32*264 + 8*256)*4;   // 110848
    const int sm5 = (2*32*137 + 2*32*264)*4;           // 102656

    cudaFuncSetAttribute(knn_kernel, cudaFuncAttributeMaxDynamicSharedMemorySize, NPTS*16);
    cudaFuncSetAttribute(gemm_fused<64,64,64,4,4,true,true,true>,
                         cudaFuncAttributeMaxDynamicSharedMemorySize, sm2);
    cudaFuncSetAttribute(gemm_fused<64,128,128,2,8,true,true,true>,
                         cudaFuncAttributeMaxDynamicSharedMemorySize, sm3);
    cudaFuncSetAttribute(gemm_fused<128,256,256,2,8,true,true,false>,
                         cudaFuncAttributeMaxDynamicSharedMemorySize, sm4);
    cudaFuncSetAttribute(gemm_fused<512,512,256,2,8,false,false,true>,
                         cudaFuncAttributeMaxDynamicSharedMemorySize, sm5);

    cudaMemsetAsync(sum, 0, 8*1024*sizeof(float), 0);
    cudaMemsetAsync(sq,  0, 8*1024*sizeof(float), 0);
    cudaMemsetAsync(mx,  0, (size_t)NG*512*4, 0);

    // launch order: gemm2 is the 4th kernel (ncu capture slot)
    knn_kernel<<<dim3(NPTS/256, BATCH), 256, NPTS*16>>>(x, idxp, W2, W3, W4, W5, wtf); // 1
    layer1_kernel<<<NG/16, 128>>>(x, idxp, W1, y1, sum+0, sq+0, mx1);                  // 2
    finalize_kernel<<<1, 64>>>(sum+0, sq+0, g1, b1, sc+0, sh+0, invR);                 // 3

    gemm_fused<64,64,64,4,4,true,true,true><<<dim3(1, NROWS/128), 128, sm2>>>(         // 4
        y1, wtf + 0, y2, sc+0, sh+0, sum+64, sq+64, mx2);
    maxtrans_kernel<64><<<NG*64/256, 256>>>(mx1, sc+0, sh+0, cat, 0);
    finalize_kernel<<<1, 64>>>(sum+64, sq+64, g2, b2, sc+64, sh+64, invR);

    gemm_fused<64,128,128,2,8,true,true,true><<<dim3(1, NROWS/128), 256, sm3>>>(
        y2, wtf + 4096, y3, sc+64, sh+64, sum+128, sq+128, mx3);
    maxtrans_kernel<64><<<NG*64/256, 256>>>(mx2, sc+64, sh+64, cat, 64);
    finalize_kernel<<<1, 128>>>(sum+128, sq+128, g3, b3, sc+128, sh+128, invR);

    gemm_fused<128,256,256,2,8,true,true,false><<<dim3(1, NROWS/128), 512, sm4>>>(
        y3, wtf + 12288, nullptr, sc+128, sh+128, sum+256, sq+256, mx4);
    maxtrans_kernel<128><<<NG*128/256, 256>>>(mx3, sc+128, sh+128, cat, 128);
    finalize_kernel<<<1, 256>>>(sum+256, sq+256, g4, b4, sc+256, sh+256, invR);
    maxtrans_kernel<256><<<NG*256/256, 256>>>(mx4, sc+256, sh+256, cat, 256);

    gemm_fused<512,512,256,2,8,false,false,true><<<dim3(2, NG/128), 512, sm5>>>(
        cat, wtf + 45056, y5, nullptr, nullptr, sum+512, sq+512, nullptr);
    finalize_kernel<<<1, 512>>>(sum+512, sq+512, g5, b5, sc+512, sh+512, invG);
    out_kernel<<<dim3(NPTS/32, 512/32, BATCH), dim3(32, 8)>>>(y5, sc+512, sh+512, out);

    (void)in_sizes; (void)n_in; (void)out_size;
}

// round 17
// speedup vs baseline: 1.0215x; 1.0215x over previous
#include <cuda_runtime.h>
#include <math.h>
#include <stdint.h>

#define NPTS  4096
#define BATCH 8
#define KNN   20
#define NG    (BATCH*NPTS)
#define NROWS (NG*KNN)
#define ENCNEG 0u   /* bottom element for encf order (memset-compatible) */

// ---------------- scratch (device globals; no allocations) ----------------
__device__ float    g_y1[(size_t)NROWS*64];
__device__ float    g_y2[(size_t)NROWS*64];
__device__ float    g_y3[(size_t)NROWS*128];
__device__ float    g_y5[(size_t)NG*512];
__device__ float    g_cat[(size_t)NG*512];
__device__ uint32_t g_mx[(size_t)NG*512];   // mx1|mx2|mx3|mx4 @ 0|64NG|128NG|256NG
__device__ int      g_idx[NROWS];
__device__ uint32_t g_wtf[307200];          // tf32 W2|W3|W4|W5 @ 0|4096|12288|45056
__device__ float    g_sum[8*1024];          // 8 replicas (anti atomic-contention)
__device__ float    g_sq[8*1024];
__device__ float    g_sc[1024];
__device__ float    g_sh[1024];

__device__ __forceinline__ uint32_t f2tf(float f) {
    uint32_t r; asm("cvt.rna.tf32.f32 %0, %1;" : "=r"(r) : "f"(f)); return r;
}
__device__ __forceinline__ void mma_tf32(float* c, const uint32_t* a, const uint32_t* b) {
    asm volatile(
        "mma.sync.aligned.m16n8k8.row.col.f32.tf32.tf32.f32 "
        "{%0,%1,%2,%3}, {%4,%5,%6,%7}, {%8,%9}, {%0,%1,%2,%3};"
        : "+f"(c[0]), "+f"(c[1]), "+f"(c[2]), "+f"(c[3])
        : "r"(a[0]), "r"(a[1]), "r"(a[2]), "r"(a[3]), "r"(b[0]), "r"(b[1]));
}
__device__ __forceinline__ uint32_t encf(float f) {
    uint32_t u = __float_as_uint(f);
    return (u & 0x80000000u) ? ~u : (u | 0x80000000u);
}
__device__ __forceinline__ float decf(uint32_t e) {
    uint32_t u = (e & 0x80000000u) ? (e & 0x7FFFFFFFu) : ~e;
    return __uint_as_float(u);
}
__device__ __forceinline__ void cp_async16(uint32_t saddr, const void* gptr) {
    asm volatile("cp.async.ca.shared.global [%0], [%1], 16;" :: "r"(saddr), "l"(gptr));
}
#define CP_COMMIT() asm volatile("cp.async.commit_group;" ::: "memory")
#define CP_WAIT0()  asm volatile("cp.async.wait_group 0;"  ::: "memory")

// -------- kNN (+ fused W f32->tf32 pre-convert using idle threads) ---------
__global__ void knn_kernel(const float* __restrict__ x, int* __restrict__ oidx,
                           const float* __restrict__ W2, const float* __restrict__ W3,
                           const float* __restrict__ W4, const float* __restrict__ W5,
                           uint32_t* __restrict__ wtf)
{
    extern __shared__ float4 pts[];
    {
        int lid = (blockIdx.y * gridDim.x + blockIdx.x) * 256 + threadIdx.x;
#pragma unroll
        for (int q = 0; q < 8; q++) {
            int i = lid + q*32768;
            if (i < 4096)  wtf[i]         = f2tf(W2[i]);
            if (i < 8192)  wtf[4096 + i]  = f2tf(W3[i]);
            if (i < 32768) wtf[12288 + i] = f2tf(W4[i]);
            wtf[45056 + i] = f2tf(W5[i]);
        }
    }
    const int b = blockIdx.y;
    const float* xb = x + (size_t)b * 3 * NPTS;
    for (int i = threadIdx.x; i < NPTS; i += 256) {
        float px = xb[i], py = xb[NPTS + i], pz = xb[2*NPTS + i];
        pts[i] = make_float4(px, py, pz, px*px + py*py + pz*pz);
    }
    __syncthreads();
    const int qi = blockIdx.x * 256 + threadIdx.x;
    const float4 q = pts[qi];
    const float q2x = 2.f*q.x, q2y = 2.f*q.y, q2z = 2.f*q.z, nqw = -q.w;

    float best[KNN]; int bidx[KNN];
#pragma unroll
    for (int m = 0; m < KNN; m++) {
        float4 p = pts[m];
        best[m] = fmaf(q2x, p.x, fmaf(q2y, p.y, fmaf(q2z, p.z, nqw - p.w)));
        bidx[m] = m;
    }
    float vmin = best[0]; int mpos = 0;
#pragma unroll
    for (int m = 1; m < KNN; m++) if (best[m] < vmin) { vmin = best[m]; mpos = m; }

    for (int j = KNN; j < NPTS; j++) {
        float4 p = pts[j];
        float v = fmaf(q2x, p.x, fmaf(q2y, p.y, fmaf(q2z, p.z, nqw - p.w)));
        if (v > vmin) {
#pragma unroll
            for (int m = 0; m < KNN; m++) if (m == mpos) { best[m] = v; bidx[m] = j; }
            vmin = best[0]; mpos = 0;
#pragma unroll
            for (int m = 1; m < KNN; m++) if (best[m] < vmin) { vmin = best[m]; mpos = m; }
        }
    }
    int* o = oidx + (size_t)(b * NPTS + qi) * KNN;
#pragma unroll
    for (int m = 0; m < KNN; m++) o[m] = bidx[m];
}

// ---------------- layer 1: gather + (6->64) + stats + raw max --------------
__global__ __launch_bounds__(128)
void layer1_kernel(const float* __restrict__ x, const int* __restrict__ idx,
                   const float* __restrict__ W1, float* __restrict__ y1,
                   float* __restrict__ sum_out, float* __restrict__ sq_out,
                   uint32_t* __restrict__ mx1)
{
    const int t    = threadIdx.x & 63;
    const int slot = threadIdx.x >> 6;
    float w[6];
#pragma unroll
    for (int c = 0; c < 6; c++) w[c] = W1[c*64 + t];
    float s = 0.f, qq = 0.f;
    const int g0 = blockIdx.x * 16;
    for (int it = 0; it < 8; it++) {
        const int g = g0 + it*2 + slot;
        const int b = g >> 12;
        const int n = g & (NPTS - 1);
        const float* xb = x + (size_t)b*3*NPTS;
        float base = fmaf(xb[n], w[3], fmaf(xb[NPTS+n], w[4], xb[2*NPTS+n]*w[5]));
        const int* ip = idx + (size_t)g*KNN;
        float* yp = y1 + (size_t)g*KNN*64 + t;
        float mxv = -3.4e38f;
#pragma unroll 4
        for (int k = 0; k < KNN; k++) {
            int j = ip[k];
            float v = fmaf(xb[j], w[0], fmaf(xb[NPTS+j], w[1], fmaf(xb[2*NPTS+j], w[2], base)));
            yp[(size_t)k*64] = v;
            s += v; qq = fmaf(v, v, qq);
            mxv = fmaxf(mxv, v);
        }
        mx1[(size_t)g*64 + t] = encf(mxv);
    }
    const int rep = (blockIdx.x & 7) * 1024;
    atomicAdd(&sum_out[rep + t], s);
    atomicAdd(&sq_out[rep + t],  qq);
}

// ---------------- bn finalize (sums 8 replicas) -----------------------------
__global__ void finalize_kernel(const float* __restrict__ sum, const float* __restrict__ sq,
                                const float* __restrict__ gam, const float* __restrict__ bet,
                                float* __restrict__ sc, float* __restrict__ sh, float inv_cnt)
{
    int c = threadIdx.x;
    float s = 0.f, q = 0.f;
#pragma unroll
    for (int r = 0; r < 8; r++) { s += sum[r*1024 + c]; q += sq[r*1024 + c]; }
    float m = s * inv_cnt;
    float v = q * inv_cnt - m*m;
    float scale = gam[c] * rsqrtf(v + 1e-5f);
    sc[c] = scale;
    sh[c] = bet[c] - m*scale;
}

// ------------- maxtrans: cat[g,off+c] = relu(dec(mx)*sc+sh) -----------------
template<int C>
__global__ void maxtrans_kernel(const uint32_t* __restrict__ mx, const float* __restrict__ sc,
                                const float* __restrict__ sh, float* __restrict__ cat, int off)
{
    int i = blockIdx.x*blockDim.x + threadIdx.x;
    int g = i / C, c = i & (C - 1);
    float v = decf(mx[i]);
    cat[(size_t)g*512 + off + c] = fmaxf(fmaf(v, sc[c], sh[c]), 0.f);
}

// ---------------------------------------------------------------------------
// Fused tf32 GEMM, 2-stage smem pipeline, de-contended bn-stats epilogue.
// Parameterized warp grid: WM x WN warps, warp tile (16*MI) x (8*NI).
// ---------------------------------------------------------------------------
template<int KD, int ND, int NT, int MI, int NI, bool BN_IN, bool MAXOUT, bool WRITE_Y>
__global__ __launch_bounds__((128/(MI*16))*(NT/(NI*8))*32)
void gemm_fused(const float* __restrict__ A, const uint32_t* __restrict__ Wtf,
                float* __restrict__ Y, const float* __restrict__ sc_in,
                const float* __restrict__ sh_in, float* __restrict__ gsum,
                float* __restrict__ gsq, uint32_t* __restrict__ gmx)
{
    constexpr int WM      = 128/(MI*16);
    constexpr int WN      = NT/(NI*8);
    constexpr int THREADS = WM*WN*32;
    constexpr int KC   = 32;
    constexpr int NCH  = KD/KC;
    constexpr int ASTR = 137;
    constexpr int BSTR = NT + 8;
    constexpr int WTN  = 8*NI;
    constexpr int AQ   = 128*(KC/4)/THREADS;
    constexpr int BQ   = KC*(NT/4)/THREADS;

    extern __shared__ uint32_t dsm[];
    uint32_t* As0 = dsm;
    uint32_t* Bs0 = dsm + 2*KC*ASTR;
    uint32_t* mxs = Bs0 + 2*KC*BSTR;
    __shared__ float ssc[KD];
    __shared__ float ssh[KD];
    const uint32_t bsAddr = (uint32_t)__cvta_generic_to_shared(Bs0);

    const int tid  = threadIdx.x;
    const int wid  = tid >> 5;
    const int lane = tid & 31;
    const int g    = lane >> 2;
    const int t    = lane & 3;
    const int warpM = wid % WM;
    const int warpN = wid / WM;
    const int rowBase = blockIdx.y * 128;
    const int colBase = blockIdx.x * NT;

    if (BN_IN)
        for (int i = tid; i < KD; i += THREADS) { ssc[i] = sc_in[i]; ssh[i] = sh_in[i]; }
    if (MAXOUT)
        for (int i = tid; i < 8*NT; i += THREADS) mxs[i] = ENCNEG;
    __syncthreads();

    float acc[MI][NI][4];
#pragma unroll
    for (int mi = 0; mi < MI; mi++)
#pragma unroll
        for (int ni = 0; ni < NI; ni++)
#pragma unroll
            for (int r = 0; r < 4; r++) acc[mi][ni][r] = 0.f;

    float4 aPre[AQ];

    // ---- prologue: chunk 0 into stage 0 ----
#pragma unroll
    for (int q = 0; q < BQ; q++) {
        int e = tid + q*THREADS;
        int k = e / (NT/4), c4 = (e % (NT/4)) * 4;
        cp_async16(bsAddr + (uint32_t)(k*BSTR + c4)*4,
                   Wtf + (size_t)k*ND + colBase + c4);
    }
    CP_COMMIT();
#pragma unroll
    for (int q = 0; q < AQ; q++) {
        int e = tid + q*THREADS;
        aPre[q] = *(const float4*)&A[(size_t)(rowBase + (e>>3))*KD + ((e&7)<<2)];
    }
    {
        uint32_t* Asw = As0;
#pragma unroll
        for (int q = 0; q < AQ; q++) {
            int e = tid + q*THREADS;
            int r = e >> 3, k4 = (e & 7) << 2;
            float4 v = aPre[q];
            if (BN_IN) {
                int c = k4;
                v.x = fmaxf(fmaf(v.x, ssc[c+0], ssh[c+0]), 0.f);
                v.y = fmaxf(fmaf(v.y, ssc[c+1], ssh[c+1]), 0.f);
                v.z = fmaxf(fmaf(v.z, ssc[c+2], ssh[c+2]), 0.f);
                v.w = fmaxf(fmaf(v.w, ssc[c+3], ssh[c+3]), 0.f);
            }
            Asw[(k4+0)*ASTR + r] = f2tf(v.x);
            Asw[(k4+1)*ASTR + r] = f2tf(v.y);
            Asw[(k4+2)*ASTR + r] = f2tf(v.z);
            Asw[(k4+3)*ASTR + r] = f2tf(v.w);
        }
    }
    CP_WAIT0();
    __syncthreads();

    for (int i = 0; i < NCH; i++) {
        const int s = i & 1;
        const int kb2 = (i+1)*KC;
        if (i + 1 < NCH) {
            const uint32_t bst = bsAddr + (uint32_t)((s^1)*KC*BSTR)*4;
#pragma unroll
            for (int q = 0; q < BQ; q++) {
                int e = tid + q*THREADS;
                int k = e / (NT/4), c4 = (e % (NT/4)) * 4;
                cp_async16(bst + (uint32_t)(k*BSTR + c4)*4,
                           Wtf + (size_t)(kb2 + k)*ND + colBase + c4);
            }
            CP_COMMIT();
#pragma unroll
            for (int q = 0; q < AQ; q++) {
                int e = tid + q*THREADS;
                aPre[q] = *(const float4*)&A[(size_t)(rowBase + (e>>3))*KD + kb2 + ((e&7)<<2)];
            }
        }
        const uint32_t* Asx = As0 + s*KC*ASTR;
        const uint32_t* Bsx = Bs0 + s*KC*BSTR;
#pragma unroll
        for (int k8 = 0; k8 < KC; k8 += 8) {
            uint32_t a[MI][4], b[NI][2];
#pragma unroll
            for (int mi = 0; mi < MI; mi++) {
                int m = warpM*(MI*16) + mi*16 + g;
                a[mi][0] = Asx[(k8 + t    )*ASTR + m    ];
                a[mi][1] = Asx[(k8 + t    )*ASTR + m + 8];
                a[mi][2] = Asx[(k8 + t + 4)*ASTR + m    ];
                a[mi][3] = Asx[(k8 + t + 4)*ASTR + m + 8];
            }
#pragma unroll
            for (int ni = 0; ni < NI; ni++) {
                int n = warpN*WTN + ni*8 + g;
                b[ni][0] = Bsx[(k8 + t    )*BSTR + n];
                b[ni][1] = Bsx[(k8 + t + 4)*BSTR + n];
            }
#pragma unroll
            for (int mi = 0; mi < MI; mi++)
#pragma unroll
                for (int ni = 0; ni < NI; ni++)
                    mma_tf32(acc[mi][ni], a[mi], b[ni]);
        }
        if (i + 1 < NCH) {
            uint32_t* Asw = As0 + (s^1)*KC*ASTR;
#pragma unroll
            for (int q = 0; q < AQ; q++) {
                int e = tid + q*THREADS;
                int r = e >> 3, k4 = (e & 7) << 2;
                float4 v = aPre[q];
                if (BN_IN) {
                    int c = kb2 + k4;
                    v.x = fmaxf(fmaf(v.x, ssc[c+0], ssh[c+0]), 0.f);
                    v.y = fmaxf(fmaf(v.y, ssc[c+1], ssh[c+1]), 0.f);
                    v.z = fmaxf(fmaf(v.z, ssc[c+2], ssh[c+2]), 0.f);
                    v.w = fmaxf(fmaf(v.w, ssc[c+3], ssh[c+3]), 0.f);
                }
                Asw[(k4+0)*ASTR + r] = f2tf(v.x);
                Asw[(k4+1)*ASTR + r] = f2tf(v.y);
                Asw[(k4+2)*ASTR + r] = f2tf(v.z);
                Asw[(k4+3)*ASTR + r] = f2tf(v.w);
            }
            CP_WAIT0();
        }
        __syncthreads();   // after this, As0 is dead -> reusable as scratch
    }

    const int col = colBase + warpN*WTN + 2*t;

    if (WRITE_Y) {
#pragma unroll
        for (int mi = 0; mi < MI; mi++) {
            size_t row0 = (size_t)rowBase + warpM*(MI*16) + mi*16 + g;
#pragma unroll
            for (int ni = 0; ni < NI; ni++) {
                *(float2*)&Y[row0*ND + col + ni*8] =
                    make_float2(acc[mi][ni][0], acc[mi][ni][1]);
                *(float2*)&Y[(row0+8)*ND + col + ni*8] =
                    make_float2(acc[mi][ni][2], acc[mi][ni][3]);
            }
        }
    }

    // ---- bn stats: shfl -> smem cross-warpM combine -> 8-replica RED ----
    float* red = (float*)As0;          // scratch: WM x NT cols x {sum,sq}
#pragma unroll
    for (int ni = 0; ni < NI; ni++) {
        float s0 = 0.f, q0 = 0.f, s1 = 0.f, q1 = 0.f;
#pragma unroll
        for (int mi = 0; mi < MI; mi++) {
            float v0 = acc[mi][ni][0], v2 = acc[mi][ni][2];
            float v1 = acc[mi][ni][1], v3 = acc[mi][ni][3];
            s0 += v0 + v2; q0 = fmaf(v0, v0, fmaf(v2, v2, q0));
            s1 += v1 + v3; q1 = fmaf(v1, v1, fmaf(v3, v3, q1));
        }
#pragma unroll
        for (int m = 4; m < 32; m <<= 1) {
            s0 += __shfl_xor_sync(0xffffffff, s0, m);
            q0 += __shfl_xor_sync(0xffffffff, q0, m);
            s1 += __shfl_xor_sync(0xffffffff, s1, m);
            q1 += __shfl_xor_sync(0xffffffff, q1, m);
        }
        if (g == 0) {
            int cl = warpN*WTN + 2*t + ni*8;
            red[(warpM*NT + cl    )*2 + 0] = s0;
            red[(warpM*NT + cl    )*2 + 1] = q0;
            red[(warpM*NT + cl + 1)*2 + 0] = s1;
            red[(warpM*NT + cl + 1)*2 + 1] = q1;
        }
    }
    __syncthreads();
    {
        const int rep = (blockIdx.y & 7) * 1024;
        for (int e = tid; e < NT; e += THREADS) {
            float s = 0.f, q = 0.f;
#pragma unroll
            for (int r = 0; r < WM; r++) {
                s += red[(r*NT+e)*2];
                q += red[(r*NT+e)*2+1];
            }
            atomicAdd(&gsum[rep + colBase + e], s);
            atomicAdd(&gsq [rep + colBase + e], q);
        }
    }

    // ---- raw max per (group, channel) ----
    if (MAXOUT) {
        const int colL = warpN*WTN + 2*t;
        const int gbase = rowBase / 20;
#pragma unroll
        for (int mi = 0; mi < MI; mi++) {
            int rl0 = warpM*(MI*16) + mi*16 + g;
            int gl0 = (rowBase + rl0) / 20 - gbase;
            int gl1 = (rowBase + rl0 + 8) / 20 - gbase;
#pragma unroll
            for (int ni = 0; ni < NI; ni++) {
                atomicMax(&mxs[gl0*NT + colL + ni*8    ], encf(acc[mi][ni][0]));
                atomicMax(&mxs[gl0*NT + colL + ni*8 + 1], encf(acc[mi][ni][1]));
                atomicMax(&mxs[gl1*NT + colL + ni*8    ], encf(acc[mi][ni][2]));
                atomicMax(&mxs[gl1*NT + colL + ni*8 + 1], encf(acc[mi][ni][3]));
            }
        }
        __syncthreads();
        int glast = (rowBase + 127) / 20;
        int ng = glast - gbase + 1;
        for (int e = tid; e < ng*NT; e += THREADS) {
            int gl = e / NT, cc = e - gl*NT;
            int gg = gbase + gl;
            uint32_t v = mxs[e];
            uint32_t* dst = &gmx[(size_t)gg*ND + colBase + cc];
            if (gg*20 >= rowBase && gg*20 + 20 <= rowBase + 128) *dst = v;
            else atomicMax(dst, v);
        }
    }
}

// ---------------- output: relu(bn(y5)) then (B,N,E) -> (B,E,N) --------------
__global__ void out_kernel(const float* __restrict__ y5, const float* __restrict__ sc,
                           const float* __restrict__ sh, float* __restrict__ out)
{
    __shared__ float tile[32][33];
    const int b = blockIdx.z;
    const int e0 = blockIdx.y * 32, n0 = blockIdx.x * 32;
    const int tx = threadIdx.x, ty = threadIdx.y;
    const int e = e0 + tx;
    const float scale = sc[e], shift = sh[e];
    for (int i = ty; i < 32; i += 8) {
        float v = y5[((size_t)b*NPTS + n0 + i)*512 + e];
        tile[i][tx] = fmaxf(fmaf(v, scale, shift), 0.f);
    }
    __syncthreads();
    for (int i = ty; i < 32; i += 8)
        out[((size_t)b*512 + e0 + i)*NPTS + n0 + tx] = tile[tx][i];
}

// ---------------------------------------------------------------------------
extern "C" void kernel_launch(void* const* d_in, const int* in_sizes, int n_in,
                              void* d_out, int out_size)
{
    const float* x  = (const float*)d_in[0];
    const float* W1 = (const float*)d_in[1];
    const float* W2 = (const float*)d_in[2];
    const float* W3 = (const float*)d_in[3];
    const float* W4 = (const float*)d_in[4];
    const float* W5 = (const float*)d_in[5];
    const float* g1 = (const float*)d_in[6];
    const float* b1 = (const float*)d_in[7];
    const float* g2 = (const float*)d_in[8];
    const float* b2 = (const float*)d_in[9];
    const float* g3 = (const float*)d_in[10];
    const float* b3 = (const float*)d_in[11];
    const float* g4 = (const float*)d_in[12];
    const float* b4 = (const float*)d_in[13];
    const float* g5 = (const float*)d_in[14];
    const float* b5 = (const float*)d_in[15];
    float* out = (float*)d_out;

    float *y1,*y2,*y3,*y5,*cat,*sum,*sq,*sc,*sh;
    uint32_t *mx,*wtf;
    int* idxp;
    cudaGetSymbolAddress((void**)&y1,  g_y1);
    cudaGetSymbolAddress((void**)&y2,  g_y2);
    cudaGetSymbolAddress((void**)&y3,  g_y3);
    cudaGetSymbolAddress((void**)&y5,  g_y5);
    cudaGetSymbolAddress((void**)&cat, g_cat);
    cudaGetSymbolAddress((void**)&mx,  g_mx);
    cudaGetSymbolAddress((void**)&idxp, g_idx);
    cudaGetSymbolAddress((void**)&wtf, g_wtf);
    cudaGetSymbolAddress((void**)&sum, g_sum);
    cudaGetSymbolAddress((void**)&sq,  g_sq);
    cudaGetSymbolAddress((void**)&sc,  g_sc);
    cudaGetSymbolAddress((void**)&sh,  g_sh);

    uint32_t* mx1 = mx;
    uint32_t* mx2 = mx + (size_t)NG*64;
    uint32_t* mx3 = mx + (size_t)NG*128;
    uint32_t* mx4 = mx + (size_t)NG*256;

    const float invR = 1.0f / (float)NROWS;
    const float invG = 1.0f / (float)NG;

    const int sm2 = (2*32*137 + 2*32*72  + 8*64 )*4;   // 55552
    const int sm3 = (2*32*137 + 2*32*136 + 8*128)*4;   // 73984
    const int sm4 = sm3;
    const int sm5 = (2*32*137 + 2*32*136)*4;           // 69888

    cudaFuncSetAttribute(knn_kernel, cudaFuncAttributeMaxDynamicSharedMemorySize, NPTS*16);
    cudaFuncSetAttribute(gemm_fused<64,64,64,4,4,true,true,true>,
                         cudaFuncAttributeMaxDynamicSharedMemorySize, sm2);
    cudaFuncSetAttribute(gemm_fused<64,128,128,4,4,true,true,true>,
                         cudaFuncAttributeMaxDynamicSharedMemorySize, sm3);
    cudaFuncSetAttribute(gemm_fused<128,256,128,2,8,true,true,false>,
                         cudaFuncAttributeMaxDynamicSharedMemorySize, sm4);
    cudaFuncSetAttribute(gemm_fused<512,512,128,2,8,false,false,true>,
                         cudaFuncAttributeMaxDynamicSharedMemorySize, sm5);

    cudaMemsetAsync(sum, 0, 8*1024*sizeof(float), 0);
    cudaMemsetAsync(sq,  0, 8*1024*sizeof(float), 0);
    cudaMemsetAsync(mx,  0, (size_t)NG*512*4, 0);

    // launch order: gemm2 is the 4th kernel (ncu capture slot)
    knn_kernel<<<dim3(NPTS/256, BATCH), 256, NPTS*16>>>(x, idxp, W2, W3, W4, W5, wtf); // 1
    layer1_kernel<<<NG/16, 128>>>(x, idxp, W1, y1, sum+0, sq+0, mx1);                  // 2
    finalize_kernel<<<1, 64>>>(sum+0, sq+0, g1, b1, sc+0, sh+0, invR);                 // 3

    gemm_fused<64,64,64,4,4,true,true,true><<<dim3(1, NROWS/128), 128, sm2>>>(         // 4
        y1, wtf + 0, y2, sc+0, sh+0, sum+64, sq+64, mx2);
    maxtrans_kernel<64><<<NG*64/256, 256>>>(mx1, sc+0, sh+0, cat, 0);
    finalize_kernel<<<1, 64>>>(sum+64, sq+64, g2, b2, sc+64, sh+64, invR);

    gemm_fused<64,128,128,4,4,true,true,true><<<dim3(1, NROWS/128), 256, sm3>>>(
        y2, wtf + 4096, y3, sc+64, sh+64, sum+128, sq+128, mx3);
    maxtrans_kernel<64><<<NG*64/256, 256>>>(mx2, sc+64, sh+64, cat, 64);
    finalize_kernel<<<1, 128>>>(sum+128, sq+128, g3, b3, sc+128, sh+128, invR);

    gemm_fused<128,256,128,2,8,true,true,false><<<dim3(2, NROWS/128), 256, sm4>>>(
        y3, wtf + 12288, nullptr, sc+128, sh+128, sum+256, sq+256, mx4);
    maxtrans_kernel<128><<<NG*128/256, 256>>>(mx3, sc+128, sh+128, cat, 128);
    finalize_kernel<<<1, 256>>>(sum+256, sq+256, g4, b4, sc+256, sh+256, invR);
    maxtrans_kernel<256><<<NG*256/256, 256>>>(mx4, sc+256, sh+256, cat, 256);

    gemm_fused<512,512,128,2,8,false,false,true><<<dim3(4, NG/128), 256, sm5>>>(
        cat, wtf + 45056, y5, nullptr, nullptr, sum+512, sq+512, nullptr);
    finalize_kernel<<<1, 512>>>(sum+512, sq+512, g5, b5, sc+512, sh+512, invG);
    out_kernel<<<dim3(NPTS/32, 512/32, BATCH), dim3(32, 8)>>>(y5, sc+512, sh+512, out);

    (void)in_sizes; (void)n_in; (void)out_size;
}